// round 15
// baseline (speedup 1.0000x reference)
#include <cuda_runtime.h>
#include <cuda_fp16.h>
#include <math.h>
#include <stdint.h>

// ---------------- problem constants ----------------
#define N_HALF 4096
#define N2     8192
#define Dm     256
#define EPSN   1e-8f
#define NBLK   64            // 8192 / 128 row blocks
#define NTILE  2080          // NBLK*(NBLK+1)/2 upper-tri tiles
#define GRID   148           // persistent CTAs

// ---------------- device scratch ----------------
__device__ __align__(16) __half gF[N2 * Dm];   // fp16 normalized rows (4MB, L2-resident)
// partials: slot o = "other" block; each (o,row) written exactly once
__device__ float g_pf [NBLK][N2];   // partial expsum (fixed shift C = 1/T)
__device__ float g_pmv[NBLK][N2];   // partial max sim
__device__ int   g_pmc[NBLK][N2];   // partial argmax col (global)
__device__ float g_tgt[N2];         // target logit per row
__device__ float g_redl[32];
__device__ int   g_redc[32];
__device__ int   g_ctr;             // finalize arrival counter
__device__ int   g_tick;            // dynamic tile ticket

// ---------------- PTX helpers (sm_80-era: compile under compute_103) ------
__device__ __forceinline__ uint32_t smem_u32(const void* p) {
    uint32_t a;
    asm("{ .reg .u64 t; cvta.to.shared.u64 t, %1; cvt.u32.u64 %0, t; }" : "=r"(a) : "l"(p));
    return a;
}
__device__ __forceinline__ void cp16(uint32_t sdst, const void* gsrc) {
    asm volatile("cp.async.cg.shared.global [%0], [%1], 16;" :: "r"(sdst), "l"(gsrc) : "memory");
}
__device__ __forceinline__ void cp_commit() {
    asm volatile("cp.async.commit_group;" ::: "memory");
}
__device__ __forceinline__ void cp_wait0() {
    asm volatile("cp.async.wait_group 0;" ::: "memory");
}
__device__ __forceinline__ void ldm_x4(uint32_t* r, uint32_t addr) {
    asm volatile("ldmatrix.sync.aligned.m8n8.x4.shared.b16 {%0,%1,%2,%3}, [%4];"
        : "=r"(r[0]), "=r"(r[1]), "=r"(r[2]), "=r"(r[3]) : "r"(addr));
}
__device__ __forceinline__ void mma16816(float* d, const uint32_t* a, uint32_t b0, uint32_t b1) {
    asm volatile("mma.sync.aligned.m16n8k16.row.col.f32.f16.f16.f32 "
        "{%0,%1,%2,%3}, {%4,%5,%6,%7}, {%8,%9}, {%0,%1,%2,%3};"
        : "+f"(d[0]), "+f"(d[1]), "+f"(d[2]), "+f"(d[3])
        : "r"(a[0]), "r"(a[1]), "r"(a[2]), "r"(a[3]), "r"(b0), "r"(b1));
}

// smem map (offsets from 1024-aligned base)
#define SM_A    0u           // 128 x 256 fp16 = 64KB (512B rows, swizzled)
#define SM_B    65536u       // 2 x 64KB full B tiles (double buffer)
// dedicated epilogue reduction scratch
#define SM_RF   196608u              // float[4 wn][128] row expsum
#define SM_RV   (SM_RF + 2048u)
#define SM_RC   (SM_RV + 2048u)
#define SM_CF   (SM_RC + 2048u)      // float[4 wm][128] col expsum
#define SM_CV   (SM_CF + 2048u)
#define SM_CC   (SM_CV + 2048u)
#define SMEM_BYTES (196608 + 12288 + 1024)

// ---------------- kernel 1: normalize + fp16 convert ----------------
__global__ void normalize_kernel(const float* __restrict__ z1,
                                 const float* __restrict__ z2) {
    if (blockIdx.x == 0 && threadIdx.x == 0) { g_ctr = 0; g_tick = GRID; }
    int row  = blockIdx.x * 8 + (threadIdx.x >> 5);
    int lane = threadIdx.x & 31;
    const float* src = (row < N_HALF) ? (z1 + (size_t)row * Dm)
                                      : (z2 + (size_t)(row - N_HALF) * Dm);
    float4 a = *reinterpret_cast<const float4*>(src + lane * 8);
    float4 b = *reinterpret_cast<const float4*>(src + lane * 8 + 4);
    float s = a.x*a.x + a.y*a.y + a.z*a.z + a.w*a.w
            + b.x*b.x + b.y*b.y + b.z*b.z + b.w*b.w;
    #pragma unroll
    for (int off = 16; off > 0; off >>= 1)
        s += __shfl_xor_sync(0xffffffffu, s, off);
    float sc = 1.0f / fmaxf(sqrtf(s), EPSN);
    float v[8] = {a.x*sc, a.y*sc, a.z*sc, a.w*sc, b.x*sc, b.y*sc, b.z*sc, b.w*sc};
    union { __half h[8]; uint4 u; } H;
    #pragma unroll
    for (int i = 0; i < 8; i++) H.h[i] = __float2half_rn(v[i]);
    *reinterpret_cast<uint4*>((uint8_t*)gF + (size_t)row * 512 + lane * 16) = H.u;
}

// ---------------- kernel 2: persistent symmetric fp16 HMMA GEMM ----------
// 148 persistent CTAs; dynamic bi-major ticket scheduling (A reuse preserved,
// near-perfect balance). 16 warps (512 thr): wm = wid&3 (32-row), wn = wid>>2
// (32-col). Full 64KB B tile double-buffered; ONE __syncthreads per tile.
// k-loop fragments software-pipelined (double-buffered ldmatrix).
__global__ void __launch_bounds__(512, 1)
sim_hmma_kernel(const float* __restrict__ lt) {
    extern __shared__ char smraw[];
    __shared__ int s_tick;
    uint32_t sb0 = smem_u32(smraw);
    uint32_t sb  = (sb0 + 1023u) & ~1023u;
    char* smb    = smraw + (sb - sb0);

    const int tid  = threadIdx.x;
    const int lane = tid & 31;
    const int wid  = tid >> 5;
    const int wm   = wid & 3;
    const int wn   = wid >> 2;

    const float invT = expf(-lt[0]);

    const uint32_t a_lo = (lane & 15) * 512u + (lane >> 4) * 16u;
    const uint32_t lxr  = (uint32_t)(lane & 7) << 4;
    const uint32_t Ab   = sb + SM_A + wm * 16384u;     // wm*32 rows * 512B

    auto loadA = [&](int bib) {
        int u = tid;
        #pragma unroll
        for (int i = 0; i < 8; i++, u += 512) {
            int rr = u >> 5, ku = u & 31;
            const uint8_t* gsrc = (const uint8_t*)gF + ((size_t)(bib * 128 + rr)) * 512 + ku * 16;
            uint32_t sdst = (sb + SM_A + (uint32_t)(rr * 512 + ku * 16))
                            ^ (uint32_t)((rr & 7) << 4);
            cp16(sdst, gsrc);
        }
        cp_commit();
    };
    auto loadB = [&](int bjb, int buf) {
        int u = tid;
        #pragma unroll
        for (int i = 0; i < 8; i++, u += 512) {
            int rr = u >> 5, ku = u & 31;
            const uint8_t* gsrc = (const uint8_t*)gF + ((size_t)(bjb * 128 + rr)) * 512 + ku * 16;
            uint32_t sdst = (sb + SM_B + (uint32_t)buf * 65536u + (uint32_t)(rr * 512 + ku * 16))
                            ^ (uint32_t)((rr & 7) << 4);
            cp16(sdst, gsrc);
        }
        cp_commit();
    };

    // first ticket for the tile after 'cur'
    if (tid == 0) s_tick = atomicAdd(&g_tick, 1);

    int cur = blockIdx.x;
    int c = 0;                 // tile counter (buffer parity)
    int loaded_bi = -1;
    bool pending = true;

    while (cur < NTILE) {
        // decode cur -> (bi, bj)
        int bi = 0;
        while ((bi + 1) * (128 - bi) / 2 <= cur) bi++;
        const int bj = bi + (cur - bi * (129 - bi) / 2);

        if (pending) {         // first tile, or A-panel change (serial stall)
            if (bi != loaded_bi) { loadA(bi); loaded_bi = bi; }
            loadB(bj, c & 1);
            pending = false;
        }
        cp_wait0();
        __syncthreads();
        const int nxt = s_tick;

        // prefetch next tile's B under current compute (same A panel only)
        if (nxt < NTILE) {
            int nbi = 0;
            while ((nbi + 1) * (128 - nbi) / 2 <= nxt) nbi++;
            const int nbj = nbi + (nxt - nbi * (129 - nbi) / 2);
            if (nbi == loaded_bi) loadB(nbj, (c + 1) & 1);
            else pending = true;
        }

        // ---- compute 128x128 tile over full K=256 (pipelined fragments) ----
        float acc[2][4][4];
        #pragma unroll
        for (int mf = 0; mf < 2; mf++)
            #pragma unroll
            for (int nb = 0; nb < 4; nb++)
                #pragma unroll
                for (int v = 0; v < 4; v++) acc[mf][nb][v] = 0.0f;

        const uint32_t Bb = sb + SM_B + (uint32_t)(c & 1) * 65536u + wn * 16384u;
        uint32_t bfr[2][2][4], af[2][2][4];
        ldm_x4(bfr[0][0], (Bb + 0u    + a_lo) ^ lxr);
        ldm_x4(bfr[0][1], (Bb + 8192u + a_lo) ^ lxr);
        ldm_x4(af[0][0],  (Ab + 0u    + a_lo) ^ lxr);
        ldm_x4(af[0][1],  (Ab + 8192u + a_lo) ^ lxr);
        #pragma unroll
        for (int kk = 0; kk < 256; kk += 16) {
            const int cu = (kk >> 4) & 1, nx = cu ^ 1;
            if (kk + 16 < 256) {
                const uint32_t k2 = (uint32_t)(kk + 16) * 2u;
                ldm_x4(bfr[nx][0], (Bb + 0u    + k2 + a_lo) ^ lxr);
                ldm_x4(bfr[nx][1], (Bb + 8192u + k2 + a_lo) ^ lxr);
                ldm_x4(af[nx][0],  (Ab + 0u    + k2 + a_lo) ^ lxr);
                ldm_x4(af[nx][1],  (Ab + 8192u + k2 + a_lo) ^ lxr);
            }
            #pragma unroll
            for (int mf = 0; mf < 2; mf++)
                #pragma unroll
                for (int g = 0; g < 2; g++) {
                    mma16816(acc[mf][g*2  ], af[cu][mf], bfr[cu][g][0], bfr[cu][g][2]);
                    mma16816(acc[mf][g*2+1], af[cu][mf], bfr[cu][g][1], bfr[cu][g][3]);
                }
        }

        // ============== epilogue: dual-direction reduction ==============
        const int  lq     = lane >> 2;
        const bool isDiag = (bi == bj);
        const bool isTgt  = (bj == bi + 32);

        float fsum[4], mv[4]; int mc[4];     // row direction (4 row slots)
        float csum[8], cv[8]; int cim[8];    // col direction (8 col slots)
        #pragma unroll
        for (int s = 0; s < 4; s++) { fsum[s] = 0.0f; mv[s] = -INFINITY; mc[s] = 0; }
        #pragma unroll
        for (int cc = 0; cc < 8; cc++) { csum[cc] = 0.0f; cv[cc] = -INFINITY; cim[cc] = 0; }

        #pragma unroll
        for (int mf = 0; mf < 2; mf++)
            #pragma unroll
            for (int nb = 0; nb < 4; nb++)
                #pragma unroll
                for (int v = 0; v < 4; v++) {
                    const int rl = wm * 32 + mf * 16 + lq + (v >> 1) * 8;
                    const int cl = wn * 32 + nb * 8 + (lane & 3) * 2 + (v & 1);
                    const float sv = acc[mf][nb][v];
                    const float e  = __expf((sv - 1.0f) * invT);
                    const bool same = (rl == cl);
                    if (isTgt && same) {
                        const float tv = sv * invT;
                        g_tgt[bi * 128 + rl]        = tv;
                        g_tgt[bi * 128 + rl + 4096] = tv;
                    }
                    if (!(isDiag && same)) {
                        const int s  = mf * 2 + (v >> 1);
                        const int cc = nb * 2 + (v & 1);
                        fsum[s] += e;
                        if (sv > mv[s]) { mv[s] = sv; mc[s] = cl; }
                        csum[cc] += e;
                        if (sv > cv[cc]) { cv[cc] = sv; cim[cc] = rl; }
                    }
                }

        // row dir: quad shfl reduce (over lane&3)
        #pragma unroll
        for (int s = 0; s < 4; s++) {
            #pragma unroll
            for (int o = 1; o < 4; o <<= 1) {
                float of = __shfl_xor_sync(0xffffffffu, fsum[s], o);
                float ov = __shfl_xor_sync(0xffffffffu, mv[s],   o);
                int   oc = __shfl_xor_sync(0xffffffffu, mc[s],   o);
                fsum[s] += of;
                if (ov > mv[s] || (ov == mv[s] && oc < mc[s])) { mv[s] = ov; mc[s] = oc; }
            }
        }
        if ((lane & 3) == 0) {
            #pragma unroll
            for (int s = 0; s < 4; s++) {
                const int rl = wm * 32 + s * 8 + lq;
                *(float*)(smb + SM_RF + (wn * 128 + rl) * 4) = fsum[s];
                *(float*)(smb + SM_RV + (wn * 128 + rl) * 4) = mv[s];
                *(int*)  (smb + SM_RC + (wn * 128 + rl) * 4) = mc[s];
            }
        }
        // col dir: shfl reduce over lq (xor 4,8,16)
        #pragma unroll
        for (int cc = 0; cc < 8; cc++) {
            #pragma unroll
            for (int o = 4; o < 32; o <<= 1) {
                float of = __shfl_xor_sync(0xffffffffu, csum[cc], o);
                float ov = __shfl_xor_sync(0xffffffffu, cv[cc],   o);
                int   oi = __shfl_xor_sync(0xffffffffu, cim[cc],  o);
                csum[cc] += of;
                if (ov > cv[cc] || (ov == cv[cc] && oi < cim[cc])) { cv[cc] = ov; cim[cc] = oi; }
            }
        }
        if (lane < 4) {
            #pragma unroll
            for (int cc = 0; cc < 8; cc++) {
                const int cl = wn * 32 + (cc >> 1) * 8 + lane * 2 + (cc & 1);
                *(float*)(smb + SM_CF + (wm * 128 + cl) * 4) = csum[cc];
                *(float*)(smb + SM_CV + (wm * 128 + cl) * 4) = cv[cc];
                *(int*)  (smb + SM_CC + (wm * 128 + cl) * 4) = cim[cc];
            }
        }
        if (tid == 0 && nxt < NTILE) s_tick = atomicAdd(&g_tick, 1);
        __syncthreads();

        if (tid < 128) {
            {   // row direction -> rows of block bi, slot bj
                const int rl = tid;
                float f = 0.0f, bv = -INFINITY; int bc = 0;
                #pragma unroll
                for (int w = 0; w < 4; w++) {
                    f += *(float*)(smb + SM_RF + (w * 128 + rl) * 4);
                    float v2 = *(float*)(smb + SM_RV + (w * 128 + rl) * 4);
                    int   c2 = *(int*)  (smb + SM_RC + (w * 128 + rl) * 4);
                    if (v2 > bv) { bv = v2; bc = c2; }
                }
                const int row = bi * 128 + rl;
                g_pf [bj][row] = f;
                g_pmv[bj][row] = bv;
                g_pmc[bj][row] = bj * 128 + bc;
            }
            if (!isDiag) {   // col direction -> rows of block bj, slot bi
                const int cl = tid;
                float f = 0.0f, bv = -INFINITY; int br = 0;
                #pragma unroll
                for (int w = 0; w < 4; w++) {
                    f += *(float*)(smb + SM_CF + (w * 128 + cl) * 4);
                    float v2 = *(float*)(smb + SM_CV + (w * 128 + cl) * 4);
                    int   r2 = *(int*)  (smb + SM_CC + (w * 128 + cl) * 4);
                    if (v2 > bv) { bv = v2; br = r2; }
                }
                const int row = bj * 128 + cl;
                g_pf [bi][row] = f;
                g_pmv[bi][row] = bv;
                g_pmc[bi][row] = bi * 128 + br;
            }
        }

        cur = nxt;
        c++;
    }
}

// ------- kernel 3: per-row reduce over 64 slots + last-block final scalar ---
__global__ void finalize_kernel(const float* __restrict__ lt, float* __restrict__ out) {
    __shared__ float sl[256];
    __shared__ int   sc[256];
    __shared__ int   isLast;
    const int tid = threadIdx.x;
    const int row = blockIdx.x * 256 + tid;
    const float invT = expf(-lt[0]);
    float fs = 0.0f, bv = -INFINITY;
    int bc = -1;
    #pragma unroll 8
    for (int o = 0; o < NBLK; o++) {
        fs += g_pf[o][row];
        float v = g_pmv[o][row];
        int   c = g_pmc[o][row];
        if (v > bv || (v == bv && c < bc)) { bv = v; bc = c; }
    }
    float lse = invT + logf(fs);
    sl[tid] = lse - g_tgt[row];
    sc[tid] = (bc == (row ^ 4096)) ? 1 : 0;
    __syncthreads();
    for (int s = 128; s > 0; s >>= 1) {
        if (tid < s) { sl[tid] += sl[tid + s]; sc[tid] += sc[tid + s]; }
        __syncthreads();
    }
    if (tid == 0) {
        g_redl[blockIdx.x] = sl[0];
        g_redc[blockIdx.x] = sc[0];
        __threadfence();
        isLast = (atomicAdd(&g_ctr, 1) == 31);
    }
    __syncthreads();
    if (isLast && tid < 32) {
        float l = g_redl[tid];
        int   c = g_redc[tid];
        #pragma unroll
        for (int o = 16; o > 0; o >>= 1) {
            l += __shfl_xor_sync(0xffffffffu, l, o);
            c += __shfl_xor_sync(0xffffffffu, c, o);
        }
        if (tid == 0) {
            out[0] = l / (float)N2;
            out[1] = 0.5f * (float)c;
        }
    }
}

extern "C" void kernel_launch(void* const* d_in, const int* in_sizes, int n_in,
                              void* d_out, int out_size) {
    const float* z1 = (const float*)d_in[0];
    const float* z2 = (const float*)d_in[1];
    const float* lt = (const float*)d_in[2];
    float* out = (float*)d_out;

    cudaFuncSetAttribute(sim_hmma_kernel,
                         cudaFuncAttributeMaxDynamicSharedMemorySize, SMEM_BYTES);

    normalize_kernel<<<N2 / 8, 256>>>(z1, z2);
    sim_hmma_kernel<<<GRID, 512, SMEM_BYTES>>>(lt);
    finalize_kernel<<<32, 256>>>(lt, out);
}

// round 16
// speedup vs baseline: 1.2224x; 1.2224x over previous
#include <cuda_runtime.h>
#include <cuda_fp16.h>
#include <math.h>
#include <stdint.h>

// ---------------- problem constants ----------------
#define N_HALF 4096
#define N2     8192
#define Dm     256
#define EPSN   1e-8f
#define NBLK   64            // 8192 / 128 row blocks
#define NTILE  2080          // NBLK*(NBLK+1)/2 upper-tri tiles
#define GRID   148           // persistent CTAs

// ---------------- device scratch ----------------
__device__ __align__(16) __half gF[N2 * Dm];   // fp16 normalized rows (4MB, L2-resident)
// partials: slot o = "other" block; each (o,row) written exactly once
__device__ float g_pf [NBLK][N2];   // partial expsum (fixed shift C = 1/T)
__device__ float g_pmv[NBLK][N2];   // partial max sim
__device__ int   g_pmc[NBLK][N2];   // partial argmax col (global)
__device__ float g_tgt[N2];         // target logit per row
__device__ float g_redl[32];
__device__ int   g_redc[32];
__device__ int   g_ctr;             // finalize arrival counter (reset in normalize)

// ---------------- PTX helpers (sm_80-era: compile under compute_103) ------
__device__ __forceinline__ uint32_t smem_u32(const void* p) {
    uint32_t a;
    asm("{ .reg .u64 t; cvta.to.shared.u64 t, %1; cvt.u32.u64 %0, t; }" : "=r"(a) : "l"(p));
    return a;
}
__device__ __forceinline__ void cp16(uint32_t sdst, const void* gsrc) {
    asm volatile("cp.async.cg.shared.global [%0], [%1], 16;" :: "r"(sdst), "l"(gsrc) : "memory");
}
__device__ __forceinline__ void cp_commit() {
    asm volatile("cp.async.commit_group;" ::: "memory");
}
__device__ __forceinline__ void cp_wait0() {
    asm volatile("cp.async.wait_group 0;" ::: "memory");
}
__device__ __forceinline__ void ldm_x4(uint32_t* r, uint32_t addr) {
    asm volatile("ldmatrix.sync.aligned.m8n8.x4.shared.b16 {%0,%1,%2,%3}, [%4];"
        : "=r"(r[0]), "=r"(r[1]), "=r"(r[2]), "=r"(r[3]) : "r"(addr));
}
__device__ __forceinline__ void mma16816(float* d, const uint32_t* a, uint32_t b0, uint32_t b1) {
    asm volatile("mma.sync.aligned.m16n8k16.row.col.f32.f16.f16.f32 "
        "{%0,%1,%2,%3}, {%4,%5,%6,%7}, {%8,%9}, {%0,%1,%2,%3};"
        : "+f"(d[0]), "+f"(d[1]), "+f"(d[2]), "+f"(d[3])
        : "r"(a[0]), "r"(a[1]), "r"(a[2]), "r"(a[3]), "r"(b0), "r"(b1));
}

// smem map (offsets from 1024-aligned base)
#define SM_A    0u           // 128 x 256 fp16 = 64KB (512B rows, swizzled)
#define SM_B    65536u       // 2 x 64KB full B tiles (double buffer)
// dedicated epilogue reduction scratch
#define SM_RF   196608u              // float[4 wn][128] row expsum
#define SM_RV   (SM_RF + 2048u)
#define SM_RC   (SM_RV + 2048u)
#define SM_CF   (SM_RC + 2048u)      // float[4 wm][128] col expsum
#define SM_CV   (SM_CF + 2048u)
#define SM_CC   (SM_CV + 2048u)
#define SMEM_BYTES (196608 + 12288 + 1024)

// ---------------- kernel 1: normalize + fp16 convert ----------------
__global__ void normalize_kernel(const float* __restrict__ z1,
                                 const float* __restrict__ z2) {
    if (blockIdx.x == 0 && threadIdx.x == 0) g_ctr = 0;   // reset finalize counter
    int row  = blockIdx.x * 8 + (threadIdx.x >> 5);
    int lane = threadIdx.x & 31;
    const float* src = (row < N_HALF) ? (z1 + (size_t)row * Dm)
                                      : (z2 + (size_t)(row - N_HALF) * Dm);
    float4 a = *reinterpret_cast<const float4*>(src + lane * 8);
    float4 b = *reinterpret_cast<const float4*>(src + lane * 8 + 4);
    float s = a.x*a.x + a.y*a.y + a.z*a.z + a.w*a.w
            + b.x*b.x + b.y*b.y + b.z*b.z + b.w*b.w;
    #pragma unroll
    for (int off = 16; off > 0; off >>= 1)
        s += __shfl_xor_sync(0xffffffffu, s, off);
    float sc = 1.0f / fmaxf(sqrtf(s), EPSN);
    float v[8] = {a.x*sc, a.y*sc, a.z*sc, a.w*sc, b.x*sc, b.y*sc, b.z*sc, b.w*sc};
    union { __half h[8]; uint4 u; } H;
    #pragma unroll
    for (int i = 0; i < 8; i++) H.h[i] = __float2half_rn(v[i]);
    *reinterpret_cast<uint4*>((uint8_t*)gF + (size_t)row * 512 + lane * 16) = H.u;
}

// ---------------- kernel 2: persistent symmetric fp16 HMMA GEMM ----------
// 148 persistent CTAs; bi-major static ranges; A panel reloads hidden by the
// diagonal-tile trick (diag tiles read A-fragments from the B buffer, so the
// new A panel streams in under the diag tile's compute). 16 warps (512 thr):
// wm = wid&3 (32-row), wn = wid>>2 (32-col). Full 64KB B tile double-buffered;
// ONE __syncthreads per tile.
__global__ void __launch_bounds__(512, 1)
sim_hmma_kernel(const float* __restrict__ lt) {
    extern __shared__ char smraw[];
    uint32_t sb0 = smem_u32(smraw);
    uint32_t sb  = (sb0 + 1023u) & ~1023u;
    char* smb    = smraw + (sb - sb0);

    const int tid  = threadIdx.x;
    const int lane = tid & 31;
    const int wid  = tid >> 5;
    const int wm   = wid & 3;
    const int wn   = wid >> 2;

    const int cta = blockIdx.x;
    const int t0  = (cta * NTILE) / GRID;
    const int t1  = ((cta + 1) * NTILE) / GRID;

    const float invT = expf(-lt[0]);

    // decode starting (bi, bj): f(bi) = bi*(129-bi)/2
    int bi = 0;
    while ((bi + 1) * (128 - bi) / 2 <= t0) bi++;
    int bj = bi + (t0 - bi * (129 - bi) / 2);

    const uint32_t a_lo = (lane & 15) * 512u + (lane >> 4) * 16u;
    const uint32_t lxr  = (uint32_t)(lane & 7) << 4;
    const uint32_t Ab   = sb + SM_A + wm * 16384u;     // wm*32 rows * 512B

    auto loadA = [&](int bib) {
        int u = tid;
        #pragma unroll
        for (int i = 0; i < 8; i++, u += 512) {
            int rr = u >> 5, ku = u & 31;
            const uint8_t* gsrc = (const uint8_t*)gF + ((size_t)(bib * 128 + rr)) * 512 + ku * 16;
            uint32_t sdst = (sb + SM_A + (uint32_t)(rr * 512 + ku * 16))
                            ^ (uint32_t)((rr & 7) << 4);
            cp16(sdst, gsrc);
        }
        cp_commit();
    };
    auto loadB = [&](int bjb, int buf) {
        int u = tid;
        #pragma unroll
        for (int i = 0; i < 8; i++, u += 512) {
            int rr = u >> 5, ku = u & 31;
            const uint8_t* gsrc = (const uint8_t*)gF + ((size_t)(bjb * 128 + rr)) * 512 + ku * 16;
            uint32_t sdst = (sb + SM_B + (uint32_t)buf * 65536u + (uint32_t)(rr * 512 + ku * 16))
                            ^ (uint32_t)((rr & 7) << 4);
            cp16(sdst, gsrc);
        }
        cp_commit();
    };

    int loaded_bi = -1;

    // first tile: serial load (A only if non-diagonal)
    if (bi != bj) { loadA(bi); loaded_bi = bi; }
    loadB(bj, t0 & 1);

    for (int t = t0; t < t1; t++) {
        cp_wait0();
        __syncthreads();

        const bool isDiag = (bi == bj);

        // next tile coordinates
        int nbi = bi, nbj = bj + 1;
        if (nbj == NBLK) { nbi++; nbj = nbi; }

        // prefetch next tile's B (always valid: across a bi change the next
        // tile is the diagonal, whose B block is the new block)
        if (t + 1 < t1) {
            loadB(nbj, (t + 1) & 1);
            // during a diagonal tile, the A panel is idle -> stream in A(bi)
            if (isDiag && loaded_bi != bi) { loadA(bi); loaded_bi = bi; }
        }

        // ---- compute 128x128 tile over full K=256 ----
        // diagonal tiles read A-fragments from the B buffer (same layout)
        const uint32_t Bbuf = sb + SM_B + (uint32_t)(t & 1) * 65536u;
        const uint32_t Aw   = isDiag ? (Bbuf + wm * 16384u) : Ab;
        const uint32_t Bw   = Bbuf + wn * 16384u;

        float acc[2][4][4];
        #pragma unroll
        for (int mf = 0; mf < 2; mf++)
            #pragma unroll
            for (int nb = 0; nb < 4; nb++)
                #pragma unroll
                for (int v = 0; v < 4; v++) acc[mf][nb][v] = 0.0f;

        #pragma unroll
        for (int kk = 0; kk < 256; kk += 16) {
            uint32_t bfr[2][4], af[2][4];
            ldm_x4(bfr[0], (Bw + 0u    + kk * 2u + a_lo) ^ lxr);
            ldm_x4(bfr[1], (Bw + 8192u + kk * 2u + a_lo) ^ lxr);
            ldm_x4(af[0],  (Aw + 0u    + kk * 2u + a_lo) ^ lxr);
            ldm_x4(af[1],  (Aw + 8192u + kk * 2u + a_lo) ^ lxr);
            #pragma unroll
            for (int mf = 0; mf < 2; mf++)
                #pragma unroll
                for (int g = 0; g < 2; g++) {
                    mma16816(acc[mf][g*2  ], af[mf], bfr[g][0], bfr[g][2]);
                    mma16816(acc[mf][g*2+1], af[mf], bfr[g][1], bfr[g][3]);
                }
        }

        // ============== epilogue: dual-direction reduction ==============
        const int  lq    = lane >> 2;
        const bool isTgt = (bj == bi + 32);

        float fsum[4], mv[4]; int mc[4];     // row direction (4 row slots)
        float csum[8], cv[8]; int cim[8];    // col direction (8 col slots)
        #pragma unroll
        for (int s = 0; s < 4; s++) { fsum[s] = 0.0f; mv[s] = -INFINITY; mc[s] = 0; }
        #pragma unroll
        for (int cc = 0; cc < 8; cc++) { csum[cc] = 0.0f; cv[cc] = -INFINITY; cim[cc] = 0; }

        #pragma unroll
        for (int mf = 0; mf < 2; mf++)
            #pragma unroll
            for (int nb = 0; nb < 4; nb++)
                #pragma unroll
                for (int v = 0; v < 4; v++) {
                    const int rl = wm * 32 + mf * 16 + lq + (v >> 1) * 8;
                    const int cl = wn * 32 + nb * 8 + (lane & 3) * 2 + (v & 1);
                    const float sv = acc[mf][nb][v];
                    const float e  = __expf((sv - 1.0f) * invT);
                    const bool same = (rl == cl);
                    if (isTgt && same) {
                        const float tv = sv * invT;
                        g_tgt[bi * 128 + rl]        = tv;
                        g_tgt[bi * 128 + rl + 4096] = tv;
                    }
                    if (!(isDiag && same)) {
                        const int s  = mf * 2 + (v >> 1);
                        const int cc = nb * 2 + (v & 1);
                        fsum[s] += e;
                        if (sv > mv[s]) { mv[s] = sv; mc[s] = cl; }
                        csum[cc] += e;
                        if (sv > cv[cc]) { cv[cc] = sv; cim[cc] = rl; }
                    }
                }

        // row dir: quad shfl reduce (over lane&3)
        #pragma unroll
        for (int s = 0; s < 4; s++) {
            #pragma unroll
            for (int o = 1; o < 4; o <<= 1) {
                float of = __shfl_xor_sync(0xffffffffu, fsum[s], o);
                float ov = __shfl_xor_sync(0xffffffffu, mv[s],   o);
                int   oc = __shfl_xor_sync(0xffffffffu, mc[s],   o);
                fsum[s] += of;
                if (ov > mv[s] || (ov == mv[s] && oc < mc[s])) { mv[s] = ov; mc[s] = oc; }
            }
        }
        if ((lane & 3) == 0) {
            #pragma unroll
            for (int s = 0; s < 4; s++) {
                const int rl = wm * 32 + s * 8 + lq;
                *(float*)(smb + SM_RF + (wn * 128 + rl) * 4) = fsum[s];
                *(float*)(smb + SM_RV + (wn * 128 + rl) * 4) = mv[s];
                *(int*)  (smb + SM_RC + (wn * 128 + rl) * 4) = mc[s];
            }
        }
        // col dir: shfl reduce over lq (xor 4,8,16)
        #pragma unroll
        for (int cc = 0; cc < 8; cc++) {
            #pragma unroll
            for (int o = 4; o < 32; o <<= 1) {
                float of = __shfl_xor_sync(0xffffffffu, csum[cc], o);
                float ov = __shfl_xor_sync(0xffffffffu, cv[cc],   o);
                int   oi = __shfl_xor_sync(0xffffffffu, cim[cc],  o);
                csum[cc] += of;
                if (ov > cv[cc] || (ov == cv[cc] && oi < cim[cc])) { cv[cc] = ov; cim[cc] = oi; }
            }
        }
        if (lane < 4) {
            #pragma unroll
            for (int cc = 0; cc < 8; cc++) {
                const int cl = wn * 32 + (cc >> 1) * 8 + lane * 2 + (cc & 1);
                *(float*)(smb + SM_CF + (wm * 128 + cl) * 4) = csum[cc];
                *(float*)(smb + SM_CV + (wm * 128 + cl) * 4) = cv[cc];
                *(int*)  (smb + SM_CC + (wm * 128 + cl) * 4) = cim[cc];
            }
        }
        __syncthreads();

        if (tid < 128) {
            {   // row direction -> rows of block bi, slot bj
                const int rl = tid;
                float f = 0.0f, bv = -INFINITY; int bc = 0;
                #pragma unroll
                for (int w = 0; w < 4; w++) {
                    f += *(float*)(smb + SM_RF + (w * 128 + rl) * 4);
                    float v2 = *(float*)(smb + SM_RV + (w * 128 + rl) * 4);
                    int   c2 = *(int*)  (smb + SM_RC + (w * 128 + rl) * 4);
                    if (v2 > bv) { bv = v2; bc = c2; }
                }
                const int row = bi * 128 + rl;
                g_pf [bj][row] = f;
                g_pmv[bj][row] = bv;
                g_pmc[bj][row] = bj * 128 + bc;
            }
            if (!isDiag) {   // col direction -> rows of block bj, slot bi
                const int cl = tid;
                float f = 0.0f, bv = -INFINITY; int br = 0;
                #pragma unroll
                for (int w = 0; w < 4; w++) {
                    f += *(float*)(smb + SM_CF + (w * 128 + cl) * 4);
                    float v2 = *(float*)(smb + SM_CV + (w * 128 + cl) * 4);
                    int   r2 = *(int*)  (smb + SM_CC + (w * 128 + cl) * 4);
                    if (v2 > bv) { bv = v2; br = r2; }
                }
                const int row = bj * 128 + cl;
                g_pf [bi][row] = f;
                g_pmv[bi][row] = bv;
                g_pmc[bi][row] = bi * 128 + br;
            }
        }

        bi = nbi; bj = nbj;
    }
}

// ------- kernel 3: per-row reduce over 64 slots + last-block final scalar ---
__global__ void finalize_kernel(const float* __restrict__ lt, float* __restrict__ out) {
    __shared__ float sl[256];
    __shared__ int   sc[256];
    __shared__ int   isLast;
    const int tid = threadIdx.x;
    const int row = blockIdx.x * 256 + tid;
    const float invT = expf(-lt[0]);
    float fs = 0.0f, bv = -INFINITY;
    int bc = -1;
    #pragma unroll 8
    for (int o = 0; o < NBLK; o++) {
        fs += g_pf[o][row];
        float v = g_pmv[o][row];
        int   c = g_pmc[o][row];
        if (v > bv || (v == bv && c < bc)) { bv = v; bc = c; }
    }
    float lse = invT + logf(fs);
    sl[tid] = lse - g_tgt[row];
    sc[tid] = (bc == (row ^ 4096)) ? 1 : 0;
    __syncthreads();
    for (int s = 128; s > 0; s >>= 1) {
        if (tid < s) { sl[tid] += sl[tid + s]; sc[tid] += sc[tid + s]; }
        __syncthreads();
    }
    if (tid == 0) {
        g_redl[blockIdx.x] = sl[0];
        g_redc[blockIdx.x] = sc[0];
        __threadfence();
        isLast = (atomicAdd(&g_ctr, 1) == 31);
    }
    __syncthreads();
    if (isLast && tid < 32) {
        float l = g_redl[tid];
        int   c = g_redc[tid];
        #pragma unroll
        for (int o = 16; o > 0; o >>= 1) {
            l += __shfl_xor_sync(0xffffffffu, l, o);
            c += __shfl_xor_sync(0xffffffffu, c, o);
        }
        if (tid == 0) {
            out[0] = l / (float)N2;
            out[1] = 0.5f * (float)c;
        }
    }
}

extern "C" void kernel_launch(void* const* d_in, const int* in_sizes, int n_in,
                              void* d_out, int out_size) {
    const float* z1 = (const float*)d_in[0];
    const float* z2 = (const float*)d_in[1];
    const float* lt = (const float*)d_in[2];
    float* out = (float*)d_out;

    cudaFuncSetAttribute(sim_hmma_kernel,
                         cudaFuncAttributeMaxDynamicSharedMemorySize, SMEM_BYTES);

    normalize_kernel<<<N2 / 8, 256>>>(z1, z2);
    sim_hmma_kernel<<<GRID, 512, SMEM_BYTES>>>(lt);
    finalize_kernel<<<32, 256>>>(lt, out);
}

// round 17
// speedup vs baseline: 1.2400x; 1.0144x over previous
#include <cuda_runtime.h>
#include <cuda_fp16.h>
#include <math.h>
#include <stdint.h>

// ---------------- problem constants ----------------
#define N_HALF 4096
#define N2     8192
#define Dm     256
#define EPSN   1e-8f
#define NBLK   64            // 8192 / 128 row blocks
#define NTILE  2080          // NBLK*(NBLK+1)/2 upper-tri tiles
#define GRID   148           // persistent CTAs

// ---------------- device scratch ----------------
__device__ __align__(16) __half gF[N2 * Dm];   // fp16 normalized rows (4MB, L2-resident)
// partials: slot o = "other" block; each (o,row) written exactly once
__device__ float g_pf [NBLK][N2];   // partial expsum (fixed shift C = 1/T)
__device__ float g_pmv[NBLK][N2];   // partial max sim
__device__ int   g_pmc[NBLK][N2];   // partial argmax col (global)
__device__ float g_tgt[N2];         // target logit per row
__device__ float g_redl[32];
__device__ int   g_redc[32];
__device__ int   g_ctr;             // finalize arrival counter (reset in normalize)

// ---------------- PTX helpers (sm_80-era: compile under compute_103) ------
__device__ __forceinline__ uint32_t smem_u32(const void* p) {
    uint32_t a;
    asm("{ .reg .u64 t; cvta.to.shared.u64 t, %1; cvt.u32.u64 %0, t; }" : "=r"(a) : "l"(p));
    return a;
}
__device__ __forceinline__ void cp16(uint32_t sdst, const void* gsrc) {
    asm volatile("cp.async.cg.shared.global [%0], [%1], 16;" :: "r"(sdst), "l"(gsrc) : "memory");
}
__device__ __forceinline__ void cp_commit() {
    asm volatile("cp.async.commit_group;" ::: "memory");
}
__device__ __forceinline__ void cp_wait0() {
    asm volatile("cp.async.wait_group 0;" ::: "memory");
}
__device__ __forceinline__ void ldm_x4(uint32_t* r, uint32_t addr) {
    asm volatile("ldmatrix.sync.aligned.m8n8.x4.shared.b16 {%0,%1,%2,%3}, [%4];"
        : "=r"(r[0]), "=r"(r[1]), "=r"(r[2]), "=r"(r[3]) : "r"(addr));
}
__device__ __forceinline__ void mma16816(float* d, const uint32_t* a, uint32_t b0, uint32_t b1) {
    asm volatile("mma.sync.aligned.m16n8k16.row.col.f32.f16.f16.f32 "
        "{%0,%1,%2,%3}, {%4,%5,%6,%7}, {%8,%9}, {%0,%1,%2,%3};"
        : "+f"(d[0]), "+f"(d[1]), "+f"(d[2]), "+f"(d[3])
        : "r"(a[0]), "r"(a[1]), "r"(a[2]), "r"(a[3]), "r"(b0), "r"(b1));
}

// smem map (offsets from 1024-aligned base)
#define SM_A    0u           // 128 x 256 fp16 = 64KB (512B rows, swizzled)
#define SM_B    65536u       // 2 x 64KB full B tiles (double buffer)
// dedicated epilogue reduction scratch
#define SM_RF   196608u              // float[4 wn][128] row expsum
#define SM_RV   (SM_RF + 2048u)
#define SM_RC   (SM_RV + 2048u)
#define SM_CF   (SM_RC + 2048u)      // float[4 wm][128] col expsum
#define SM_CV   (SM_CF + 2048u)
#define SM_CC   (SM_CV + 2048u)
#define SMEM_BYTES (196608 + 12288 + 1024)

// ---------------- kernel 1: normalize + fp16 convert ----------------
__global__ void normalize_kernel(const float* __restrict__ z1,
                                 const float* __restrict__ z2) {
    if (blockIdx.x == 0 && threadIdx.x == 0) g_ctr = 0;   // reset finalize counter
    int row  = blockIdx.x * 8 + (threadIdx.x >> 5);
    int lane = threadIdx.x & 31;
    const float* src = (row < N_HALF) ? (z1 + (size_t)row * Dm)
                                      : (z2 + (size_t)(row - N_HALF) * Dm);
    float4 a = *reinterpret_cast<const float4*>(src + lane * 8);
    float4 b = *reinterpret_cast<const float4*>(src + lane * 8 + 4);
    float s = a.x*a.x + a.y*a.y + a.z*a.z + a.w*a.w
            + b.x*b.x + b.y*b.y + b.z*b.z + b.w*b.w;
    #pragma unroll
    for (int off = 16; off > 0; off >>= 1)
        s += __shfl_xor_sync(0xffffffffu, s, off);
    float sc = 1.0f / fmaxf(sqrtf(s), EPSN);
    float v[8] = {a.x*sc, a.y*sc, a.z*sc, a.w*sc, b.x*sc, b.y*sc, b.z*sc, b.w*sc};
    union { __half h[8]; uint4 u; } H;
    #pragma unroll
    for (int i = 0; i < 8; i++) H.h[i] = __float2half_rn(v[i]);
    *reinterpret_cast<uint4*>((uint8_t*)gF + (size_t)row * 512 + lane * 16) = H.u;
}

// ---- per-element scan of the PREVIOUS tile's accumulators (2 per k-iter) --
#define SCAN_E(PACC, E) do {                                                  \
    const int smf = (E) >> 4, snb = ((E) >> 2) & 3, svv = (E) & 3;            \
    const int rl = wm * 32 + smf * 16 + lq + (svv >> 1) * 8;                  \
    const int cl = wn * 32 + snb * 8 + (lane & 3) * 2 + (svv & 1);            \
    const float sv = PACC[smf][snb][svv];                                     \
    const float ex = __expf(fmaf(sv, invT, -invT));                           \
    const bool same = (rl == cl);                                             \
    if (pTgt && same) {                                                       \
        const float tv = sv * invT;                                           \
        g_tgt[pbi * 128 + rl]        = tv;                                    \
        g_tgt[pbi * 128 + rl + 4096] = tv;                                    \
    }                                                                         \
    if (!(pDiag && same)) {                                                   \
        const int ss = smf * 2 + (svv >> 1), scc = snb * 2 + (svv & 1);       \
        fsum[ss] += ex; if (sv > mv[ss]) { mv[ss] = sv; mc[ss] = cl; }        \
        csum[scc] += ex; if (sv > cv[scc]) { cv[scc] = sv; cim[scc] = rl; }   \
    }                                                                         \
} while (0)

#define SCAN_ALL(PACC) do {                                                   \
    _Pragma("unroll")                                                         \
    for (int e = 0; e < 32; e++) SCAN_E(PACC, e);                             \
} while (0)

#define ZACC(ACC) do {                                                        \
    _Pragma("unroll")                                                         \
    for (int zf = 0; zf < 2; zf++)                                            \
        _Pragma("unroll")                                                     \
        for (int zb = 0; zb < 4; zb++)                                        \
            _Pragma("unroll")                                                 \
            for (int zv = 0; zv < 4; zv++) ACC[zf][zb][zv] = 0.0f;            \
} while (0)

// k-loop: fill ACC for the current tile; optionally scan PACC (prev tile)
#define KLOOP(ACC, PACC, DOSCAN) do {                                         \
    _Pragma("unroll")                                                         \
    for (int kk = 0; kk < 256; kk += 16) {                                    \
        uint32_t bfr[2][4], af[2][4];                                         \
        ldm_x4(bfr[0], (Bw + 0u    + kk * 2u + a_lo) ^ lxr);                  \
        ldm_x4(bfr[1], (Bw + 8192u + kk * 2u + a_lo) ^ lxr);                  \
        ldm_x4(af[0],  (Aw + 0u    + kk * 2u + a_lo) ^ lxr);                  \
        ldm_x4(af[1],  (Aw + 8192u + kk * 2u + a_lo) ^ lxr);                  \
        if (DOSCAN) { SCAN_E(PACC, (kk >> 4) * 2); SCAN_E(PACC, (kk >> 4) * 2 + 1); } \
        _Pragma("unroll")                                                     \
        for (int mf = 0; mf < 2; mf++)                                        \
            _Pragma("unroll")                                                 \
            for (int g = 0; g < 2; g++) {                                     \
                mma16816(ACC[mf][g*2  ], af[mf], bfr[g][0], bfr[g][2]);       \
                mma16816(ACC[mf][g*2+1], af[mf], bfr[g][1], bfr[g][3]);       \
            }                                                                 \
    }                                                                         \
} while (0)

#define INITSTATE do {                                                        \
    _Pragma("unroll")                                                         \
    for (int s = 0; s < 4; s++) { fsum[s] = 0.0f; mv[s] = -INFINITY; mc[s] = 0; } \
    _Pragma("unroll")                                                         \
    for (int cc = 0; cc < 8; cc++) { csum[cc] = 0.0f; cv[cc] = -INFINITY; cim[cc] = 0; } \
} while (0)

// shfl/smem reductions + global writes for the PREVIOUS tile (pbi, pbj)
#define REDUCE_WRITE do {                                                     \
    _Pragma("unroll")                                                         \
    for (int s = 0; s < 4; s++) {                                             \
        _Pragma("unroll")                                                     \
        for (int o = 1; o < 4; o <<= 1) {                                     \
            float of = __shfl_xor_sync(0xffffffffu, fsum[s], o);              \
            float ov = __shfl_xor_sync(0xffffffffu, mv[s],   o);              \
            int   oc = __shfl_xor_sync(0xffffffffu, mc[s],   o);              \
            fsum[s] += of;                                                    \
            if (ov > mv[s] || (ov == mv[s] && oc < mc[s])) { mv[s] = ov; mc[s] = oc; } \
        }                                                                     \
    }                                                                         \
    if ((lane & 3) == 0) {                                                    \
        _Pragma("unroll")                                                     \
        for (int s = 0; s < 4; s++) {                                         \
            const int rl = wm * 32 + s * 8 + lq;                              \
            *(float*)(smb + SM_RF + (wn * 128 + rl) * 4) = fsum[s];           \
            *(float*)(smb + SM_RV + (wn * 128 + rl) * 4) = mv[s];             \
            *(int*)  (smb + SM_RC + (wn * 128 + rl) * 4) = mc[s];             \
        }                                                                     \
    }                                                                         \
    _Pragma("unroll")                                                         \
    for (int cc = 0; cc < 8; cc++) {                                          \
        _Pragma("unroll")                                                     \
        for (int o = 4; o < 32; o <<= 1) {                                    \
            float of = __shfl_xor_sync(0xffffffffu, csum[cc], o);             \
            float ov = __shfl_xor_sync(0xffffffffu, cv[cc],   o);             \
            int   oi = __shfl_xor_sync(0xffffffffu, cim[cc],  o);             \
            csum[cc] += of;                                                   \
            if (ov > cv[cc] || (ov == cv[cc] && oi < cim[cc])) { cv[cc] = ov; cim[cc] = oi; } \
        }                                                                     \
    }                                                                         \
    if (lane < 4) {                                                           \
        _Pragma("unroll")                                                     \
        for (int cc = 0; cc < 8; cc++) {                                      \
            const int cl = wn * 32 + (cc >> 1) * 8 + lane * 2 + (cc & 1);     \
            *(float*)(smb + SM_CF + (wm * 128 + cl) * 4) = csum[cc];          \
            *(float*)(smb + SM_CV + (wm * 128 + cl) * 4) = cv[cc];            \
            *(int*)  (smb + SM_CC + (wm * 128 + cl) * 4) = cim[cc];           \
        }                                                                     \
    }                                                                         \
    __syncthreads();                                                          \
    if (tid < 128) {                                                          \
        {                                                                     \
            const int rl = tid;                                               \
            float f = 0.0f, bv = -INFINITY; int bc = 0;                       \
            _Pragma("unroll")                                                 \
            for (int w = 0; w < 4; w++) {                                     \
                f += *(float*)(smb + SM_RF + (w * 128 + rl) * 4);             \
                float v2 = *(float*)(smb + SM_RV + (w * 128 + rl) * 4);       \
                int   c2 = *(int*)  (smb + SM_RC + (w * 128 + rl) * 4);       \
                if (v2 > bv) { bv = v2; bc = c2; }                            \
            }                                                                 \
            const int row = pbi * 128 + rl;                                   \
            g_pf [pbj][row] = f;                                              \
            g_pmv[pbj][row] = bv;                                             \
            g_pmc[pbj][row] = pbj * 128 + bc;                                 \
        }                                                                     \
        if (!pDiag) {                                                         \
            const int cl = tid;                                               \
            float f = 0.0f, bv = -INFINITY; int br = 0;                       \
            _Pragma("unroll")                                                 \
            for (int w = 0; w < 4; w++) {                                     \
                f += *(float*)(smb + SM_CF + (w * 128 + cl) * 4);             \
                float v2 = *(float*)(smb + SM_CV + (w * 128 + cl) * 4);       \
                int   r2 = *(int*)  (smb + SM_CC + (w * 128 + cl) * 4);       \
                if (v2 > bv) { bv = v2; br = r2; }                            \
            }                                                                 \
            const int row = pbj * 128 + cl;                                   \
            g_pf [pbi][row] = f;                                              \
            g_pmv[pbi][row] = bv;                                             \
            g_pmc[pbi][row] = pbi * 128 + br;                                 \
        }                                                                     \
    }                                                                         \
} while (0)

// ---------------- kernel 2: persistent symmetric fp16 HMMA GEMM ----------
// R15 schedule (bi-major static ranges, diag-trick A hiding, 64KB B double
// buffer, one sync/tile) + cross-tile epilogue pipelining: each tile's
// element scan (exp/max/sum) runs inside the NEXT tile's k-loop.
__global__ void __launch_bounds__(512, 1)
sim_hmma_kernel(const float* __restrict__ lt) {
    extern __shared__ char smraw[];
    uint32_t sb0 = smem_u32(smraw);
    uint32_t sb  = (sb0 + 1023u) & ~1023u;
    char* smb    = smraw + (sb - sb0);

    const int tid  = threadIdx.x;
    const int lane = tid & 31;
    const int wid  = tid >> 5;
    const int wm   = wid & 3;
    const int wn   = wid >> 2;
    const int lq   = lane >> 2;

    const int cta = blockIdx.x;
    const int t0  = (cta * NTILE) / GRID;
    const int t1  = ((cta + 1) * NTILE) / GRID;

    const float invT = expf(-lt[0]);

    // decode starting (bi, bj): f(bi) = bi*(129-bi)/2
    int bi = 0;
    while ((bi + 1) * (128 - bi) / 2 <= t0) bi++;
    int bj = bi + (t0 - bi * (129 - bi) / 2);

    const uint32_t a_lo = (lane & 15) * 512u + (lane >> 4) * 16u;
    const uint32_t lxr  = (uint32_t)(lane & 7) << 4;
    const uint32_t Ab   = sb + SM_A + wm * 16384u;     // wm*32 rows * 512B

    auto loadA = [&](int bib) {
        int u = tid;
        #pragma unroll
        for (int i = 0; i < 8; i++, u += 512) {
            int rr = u >> 5, ku = u & 31;
            const uint8_t* gsrc = (const uint8_t*)gF + ((size_t)(bib * 128 + rr)) * 512 + ku * 16;
            uint32_t sdst = (sb + SM_A + (uint32_t)(rr * 512 + ku * 16))
                            ^ (uint32_t)((rr & 7) << 4);
            cp16(sdst, gsrc);
        }
        cp_commit();
    };
    auto loadB = [&](int bjb, int buf) {
        int u = tid;
        #pragma unroll
        for (int i = 0; i < 8; i++, u += 512) {
            int rr = u >> 5, ku = u & 31;
            const uint8_t* gsrc = (const uint8_t*)gF + ((size_t)(bjb * 128 + rr)) * 512 + ku * 16;
            uint32_t sdst = (sb + SM_B + (uint32_t)buf * 65536u + (uint32_t)(rr * 512 + ku * 16))
                            ^ (uint32_t)((rr & 7) << 4);
            cp16(sdst, gsrc);
        }
        cp_commit();
    };

    float accA[2][4][4], accB[2][4][4];
    float fsum[4], mv[4]; int mc[4];
    float csum[8], cv[8]; int cim[8];
    int  pbi = 0, pbj = 0;
    bool pDiag = false, pTgt = false;

    int loaded_bi = -1;

    // first tile: serial load (A only if non-diagonal)
    if (bi != bj) { loadA(bi); loaded_bi = bi; }
    loadB(bj, t0 & 1);
    INITSTATE;

    // ---------- peel first tile (fill accA, no scan) ----------
    {
        cp_wait0();
        __syncthreads();
        const bool isDiag = (bi == bj);
        int nbi = bi, nbj = bj + 1;
        if (nbj == NBLK) { nbi++; nbj = nbi; }
        if (t0 + 1 < t1) {
            loadB(nbj, (t0 + 1) & 1);
            if (isDiag && loaded_bi != bi) { loadA(bi); loaded_bi = bi; }
        }
        const uint32_t Bbuf = sb + SM_B + (uint32_t)(t0 & 1) * 65536u;
        const uint32_t Aw   = isDiag ? (Bbuf + wm * 16384u) : Ab;
        const uint32_t Bw   = Bbuf + wn * 16384u;
        ZACC(accA);
        KLOOP(accA, accA, false);
        pbi = bi; pbj = bj; pDiag = isDiag; pTgt = (bj == bi + 32);
        bi = nbi; bj = nbj;
    }

    // ---------- main loop: k-loop of t with scan of t-1 ----------
    int par = 0;   // 0: accA holds prev (scan A, fill B); 1: vice versa
    for (int t = t0 + 1; t < t1; t++) {
        cp_wait0();
        __syncthreads();
        const bool isDiag = (bi == bj);
        int nbi = bi, nbj = bj + 1;
        if (nbj == NBLK) { nbi++; nbj = nbi; }
        if (t + 1 < t1) {
            loadB(nbj, (t + 1) & 1);
            if (isDiag && loaded_bi != bi) { loadA(bi); loaded_bi = bi; }
        }
        const uint32_t Bbuf = sb + SM_B + (uint32_t)(t & 1) * 65536u;
        const uint32_t Aw   = isDiag ? (Bbuf + wm * 16384u) : Ab;
        const uint32_t Bw   = Bbuf + wn * 16384u;

        if (par == 0) { ZACC(accB); KLOOP(accB, accA, true); }
        else          { ZACC(accA); KLOOP(accA, accB, true); }

        REDUCE_WRITE;            // writes tile (pbi, pbj)
        INITSTATE;

        pbi = bi; pbj = bj; pDiag = isDiag; pTgt = (bj == bi + 32);
        bi = nbi; bj = nbj;
        par ^= 1;
    }

    // ---------- tail: scan + reduce the last tile ----------
    __syncthreads();             // previous REDUCE's smem reads done
    if (par == 0) SCAN_ALL(accA); else SCAN_ALL(accB);
    REDUCE_WRITE;
}

// ------- kernel 3: per-row reduce over 64 slots + last-block final scalar ---
__global__ void finalize_kernel(const float* __restrict__ lt, float* __restrict__ out) {
    __shared__ float sl[256];
    __shared__ int   sc[256];
    __shared__ int   isLast;
    const int tid = threadIdx.x;
    const int row = blockIdx.x * 256 + tid;
    const float invT = expf(-lt[0]);
    float fs = 0.0f, bv = -INFINITY;
    int bc = -1;
    #pragma unroll 8
    for (int o = 0; o < NBLK; o++) {
        fs += g_pf[o][row];
        float v = g_pmv[o][row];
        int   c = g_pmc[o][row];
        if (v > bv || (v == bv && c < bc)) { bv = v; bc = c; }
    }
    float lse = invT + logf(fs);
    sl[tid] = lse - g_tgt[row];
    sc[tid] = (bc == (row ^ 4096)) ? 1 : 0;
    __syncthreads();
    for (int s = 128; s > 0; s >>= 1) {
        if (tid < s) { sl[tid] += sl[tid + s]; sc[tid] += sc[tid + s]; }
        __syncthreads();
    }
    if (tid == 0) {
        g_redl[blockIdx.x] = sl[0];
        g_redc[blockIdx.x] = sc[0];
        __threadfence();
        isLast = (atomicAdd(&g_ctr, 1) == 31);
    }
    __syncthreads();
    if (isLast && tid < 32) {
        float l = g_redl[tid];
        int   c = g_redc[tid];
        #pragma unroll
        for (int o = 16; o > 0; o >>= 1) {
            l += __shfl_xor_sync(0xffffffffu, l, o);
            c += __shfl_xor_sync(0xffffffffu, c, o);
        }
        if (tid == 0) {
            out[0] = l / (float)N2;
            out[1] = 0.5f * (float)c;
        }
    }
}

extern "C" void kernel_launch(void* const* d_in, const int* in_sizes, int n_in,
                              void* d_out, int out_size) {
    const float* z1 = (const float*)d_in[0];
    const float* z2 = (const float*)d_in[1];
    const float* lt = (const float*)d_in[2];
    float* out = (float*)d_out;

    cudaFuncSetAttribute(sim_hmma_kernel,
                         cudaFuncAttributeMaxDynamicSharedMemorySize, SMEM_BYTES);

    normalize_kernel<<<N2 / 8, 256>>>(z1, z2);
    sim_hmma_kernel<<<GRID, 512, SMEM_BYTES>>>(lt);
    finalize_kernel<<<32, 256>>>(lt, out);
}